// round 14
// baseline (speedup 1.0000x reference)
#include <cuda_runtime.h>
#include <cstdint>

// ---------------------------------------------------------------------------
// GIN graph network, fp32. N=100000, E=1.25M, D=64, L=4, B=2048.
// CSR-by-dst edge aggregation (half-warp-per-edge float4 gather),
// B-stationary mma.sync tf32 3-pass GEMMs, separate bn2_apply.
// ---------------------------------------------------------------------------

#define MAXN 100000
#define MAXE 1250000
#define MAXB 2048

__device__ __align__(16) float g_h[(size_t)MAXN * 64];
__device__ __align__(16) float g_agg[(size_t)MAXN * 64];   // z buffer / y2 buffer
__device__ __align__(16) float g_y1[(size_t)MAXN * 128];
__device__ __align__(16) float g_stats[384];  // [0:128) sum1 [128:256) sq1 [256:320) sum2 [320:384) sq2
__device__ float g_cnt[MAXB];
__device__ int g_off[MAXN + 1];
__device__ int g_cur[MAXN];
__device__ int g_bsum[128];
__device__ __align__(8) int2 g_csr[MAXE];     // (src, combo) grouped by dst

__device__ __forceinline__ void red_add_v4(float* addr, float4 v) {
    asm volatile("red.global.add.v4.f32 [%0], {%1,%2,%3,%4};"
                 :: "l"(addr), "f"(v.x), "f"(v.y), "f"(v.z), "f"(v.w)
                 : "memory");
}

__device__ __forceinline__ float tf32_hi(float x) {
    return __uint_as_float(__float_as_uint(x) & 0xFFFFE000u);
}

__device__ __forceinline__ void mma8f(float* d, float a0, float a1, float a2, float a3,
                                      float b0, float b1) {
    asm volatile(
        "mma.sync.aligned.m16n8k8.row.col.f32.tf32.tf32.f32 "
        "{%0,%1,%2,%3}, {%4,%5,%6,%7}, {%8,%9}, {%0,%1,%2,%3};"
        : "+f"(d[0]), "+f"(d[1]), "+f"(d[2]), "+f"(d[3])
        : "r"(__float_as_uint(a0)), "r"(__float_as_uint(a1)),
          "r"(__float_as_uint(a2)), "r"(__float_as_uint(a3)),
          "r"(__float_as_uint(b0)), "r"(__float_as_uint(b1)));
}

// ---------------------------------------------------------------------------
// Atom encoder
// ---------------------------------------------------------------------------
__global__ __launch_bounds__(256) void atom_kernel(
    const float* __restrict__ atom_emb, const int* __restrict__ x_feat, int n)
{
    int wi = blockIdx.x * 256 + threadIdx.x;
    int nid = wi >> 4;
    if (nid >= n) return;
    int c = wi & 15;
    const float4* ae = (const float4*)atom_emb;
    float4 acc = make_float4(0.f, 0.f, 0.f, 0.f);
#pragma unroll
    for (int f = 0; f < 9; f++) {
        int idx = __ldg(&x_feat[nid * 9 + f]);
        float4 v = ae[(f * 128 + idx) * 16 + c];
        acc.x += v.x; acc.y += v.y; acc.z += v.z; acc.w += v.w;
    }
    ((float4*)g_h)[(size_t)nid * 16 + c] = acc;
}

// ---------------------------------------------------------------------------
// CSR build (one-time): histogram -> scan -> scatter
// ---------------------------------------------------------------------------
__global__ __launch_bounds__(256) void clear_off_kernel(int n)
{
    int i = blockIdx.x * 256 + threadIdx.x;
    if (i <= n) g_off[i] = 0;
}

__global__ __launch_bounds__(256) void hist_kernel(
    const int* __restrict__ edge_index, int e)
{
    int i = blockIdx.x * 256 + threadIdx.x;
    if (i >= e) return;
    atomicAdd(&g_off[__ldg(&edge_index[e + i]) + 1], 1);
}

__global__ __launch_bounds__(1024) void scan_partial_kernel(int n)
{
    int tid = threadIdx.x;
    int j = 1 + blockIdx.x * 1024 + tid;
    int v = (j <= n) ? g_off[j] : 0;
    __shared__ int ws[32];
    int lane = tid & 31, w = tid >> 5;
#pragma unroll
    for (int off = 16; off > 0; off >>= 1) v += __shfl_down_sync(0xffffffffu, v, off);
    if (lane == 0) ws[w] = v;
    __syncthreads();
    if (w == 0) {
        int t = ws[lane];
#pragma unroll
        for (int off = 16; off > 0; off >>= 1) t += __shfl_down_sync(0xffffffffu, t, off);
        if (lane == 0) g_bsum[blockIdx.x] = t;
    }
}

__global__ void scan_bsums_kernel(int nblocks)
{
    if (threadIdx.x == 0) {
        int carry = 0;
        for (int b = 0; b < nblocks; b++) {
            int t = g_bsum[b];
            g_bsum[b] = carry;
            carry += t;
        }
    }
}

__global__ __launch_bounds__(1024) void scan_final_kernel(int n)
{
    int tid = threadIdx.x;
    int j = 1 + blockIdx.x * 1024 + tid;
    int v = (j <= n) ? g_off[j] : 0;
    __shared__ int ws[32];
    int lane = tid & 31, w = tid >> 5;
    int x = v;
#pragma unroll
    for (int off = 1; off < 32; off <<= 1) {
        int t = __shfl_up_sync(0xffffffffu, x, off);
        if (lane >= off) x += t;
    }
    if (lane == 31) ws[w] = x;
    __syncthreads();
    if (w == 0) {
        int t = ws[lane];
#pragma unroll
        for (int off = 1; off < 32; off <<= 1) {
            int u = __shfl_up_sync(0xffffffffu, t, off);
            if (lane >= off) t += u;
        }
        ws[lane] = t;
    }
    __syncthreads();
    int pref = (w > 0) ? ws[w - 1] : 0;
    if (j <= n) g_off[j] = x + pref + g_bsum[blockIdx.x];
}

__global__ __launch_bounds__(256) void copy_cur_kernel(int n)
{
    int i = blockIdx.x * 256 + threadIdx.x;
    if (i < n) g_cur[i] = g_off[i];
}

__global__ __launch_bounds__(256) void scatter_kernel(
    const int* __restrict__ edge_index, const int* __restrict__ edge_attr, int e)
{
    int i = blockIdx.x * 256 + threadIdx.x;
    if (i >= e) return;
    int src = __ldg(&edge_index[i]);
    int dst = __ldg(&edge_index[e + i]);
    int a0 = __ldg(&edge_attr[3 * i + 0]);
    int a1 = __ldg(&edge_attr[3 * i + 1]);
    int a2 = __ldg(&edge_attr[3 * i + 2]);
    int pos = atomicAdd(&g_cur[dst], 1);
    g_csr[pos] = make_int2(src, a0 * 25 + a1 * 5 + a2);
}

__global__ __launch_bounds__(256) void clear_pool_kernel(float* __restrict__ gout, int b)
{
    int i = blockIdx.x * 256 + threadIdx.x;
    if (i < b * 64) gout[i] = 0.f;
    if (i < b) g_cnt[i] = 0.f;
}

// ---------------------------------------------------------------------------
// Edge kernel (CSR): warp-per-node, HALF-WARP-PER-EDGE float4 gather.
// Lanes 0-15 process even edges, 16-31 odd edges; lane covers one float4
// chunk (c4 = lane & 15). Halves merged with shfl_xor(16) per node.
// z = (1+eps)*h[nid] + sum relu(h[src] + table[combo]) -> g_agg.
// Block 0 zeroes g_stats.
// ---------------------------------------------------------------------------
__global__ __launch_bounds__(256) void edge_csr_kernel(
    const float* __restrict__ bond_emb_l, const float* __restrict__ epsp, int n)
{
    __shared__ __align__(16) float table[125 * 64];   // 31.25 KB

    if (blockIdx.x == 0 && threadIdx.x < 128) {
        g_stats[threadIdx.x] = 0.f;
        g_stats[128 + threadIdx.x] = 0.f;
        g_stats[256 + threadIdx.x] = 0.f;
    }

    const float4* b4 = (const float4*)bond_emb_l;     // [3,8,16] float4
    for (int t = threadIdx.x; t < 2000; t += 256) {
        int combo = t >> 4, c4i = t & 15;
        int a0 = combo / 25;
        int rr = combo - a0 * 25;
        int a1 = rr / 5;
        int a2 = rr - a1 * 5;
        float4 v0 = b4[a0 * 16 + c4i];
        float4 v1 = b4[(8 + a1) * 16 + c4i];
        float4 v2 = b4[(16 + a2) * 16 + c4i];
        float4 s;
        s.x = v0.x + v1.x + v2.x;
        s.y = v0.y + v1.y + v2.y;
        s.z = v0.z + v1.z + v2.z;
        s.w = v0.w + v1.w + v2.w;
        ((float4*)table)[t] = s;
    }
    __syncthreads();

    float epsv = 1.0f + __ldg(epsp);
    int lane = threadIdx.x & 31;
    int w = threadIdx.x >> 5;
    int half = lane >> 4;      // 0: even edges, 1: odd edges
    int c4 = lane & 15;        // float4 chunk
    const float4* tb4 = (const float4*)table;
    const float4* h4 = (const float4*)g_h;

    for (int nid = blockIdx.x * 8 + w; nid < n; nid += gridDim.x * 8) {
        int s = __ldg(&g_off[nid]);
        int epos = __ldg(&g_off[nid + 1]);
        float4 a0 = make_float4(0.f, 0.f, 0.f, 0.f);
        float4 a1 = make_float4(0.f, 0.f, 0.f, 0.f);
        int j = s + half;
        // unroll 2: edges j and j+2 per iteration (per half-warp)
        for (; j + 2 < epos; j += 4) {
            int2 m0 = __ldg(&g_csr[j]);
            int2 m1 = __ldg(&g_csr[j + 2]);
            float4 h0 = h4[(size_t)m0.x * 16 + c4];
            float4 h1 = h4[(size_t)m1.x * 16 + c4];
            float4 e0 = tb4[m0.y * 16 + c4];
            float4 e1 = tb4[m1.y * 16 + c4];
            a0.x += fmaxf(h0.x + e0.x, 0.f);
            a0.y += fmaxf(h0.y + e0.y, 0.f);
            a0.z += fmaxf(h0.z + e0.z, 0.f);
            a0.w += fmaxf(h0.w + e0.w, 0.f);
            a1.x += fmaxf(h1.x + e1.x, 0.f);
            a1.y += fmaxf(h1.y + e1.y, 0.f);
            a1.z += fmaxf(h1.z + e1.z, 0.f);
            a1.w += fmaxf(h1.w + e1.w, 0.f);
        }
        if (j < epos) {
            int2 m0 = __ldg(&g_csr[j]);
            float4 h0 = h4[(size_t)m0.x * 16 + c4];
            float4 e0 = tb4[m0.y * 16 + c4];
            a0.x += fmaxf(h0.x + e0.x, 0.f);
            a0.y += fmaxf(h0.y + e0.y, 0.f);
            a0.z += fmaxf(h0.z + e0.z, 0.f);
            a0.w += fmaxf(h0.w + e0.w, 0.f);
        }
        a0.x += a1.x; a0.y += a1.y; a0.z += a1.z; a0.w += a1.w;
        // merge halves (same c4 columns in lane and lane^16)
        a0.x += __shfl_xor_sync(0xffffffffu, a0.x, 16);
        a0.y += __shfl_xor_sync(0xffffffffu, a0.y, 16);
        a0.z += __shfl_xor_sync(0xffffffffu, a0.z, 16);
        a0.w += __shfl_xor_sync(0xffffffffu, a0.w, 16);
        if (half == 0) {
            float4 hd = h4[(size_t)nid * 16 + c4];
            float4 z;
            z.x = fmaf(epsv, hd.x, a0.x);
            z.y = fmaf(epsv, hd.y, a0.y);
            z.z = fmaf(epsv, hd.z, a0.z);
            z.w = fmaf(epsv, hd.w, a0.w);
            ((float4*)g_agg)[(size_t)nid * 16 + c4] = z;
        }
    }
}

// ---------------------------------------------------------------------------
// GEMM1 (tensor, B-stationary): z (g_agg) -> y1 = z@W1+b1 (g_y1). Fused BN1
// stats.
// ---------------------------------------------------------------------------
__global__ __launch_bounds__(256, 2) void gemm1_tc_kernel(
    const float* __restrict__ W1, const float* __restrict__ b1, int n, int ntiles)
{
    __shared__ float Zh[2][16][68];
    __shared__ float Zl[2][16][68];

    int tid = threadIdx.x;
    int wid = tid >> 5;
    int lane = tid & 31;
    int g = lane >> 2, tt = lane & 3;
    int nt0 = wid * 16;

    float wh[8][2][2], wl[8][2][2];
#pragma unroll
    for (int ks = 0; ks < 8; ks++)
#pragma unroll
        for (int t2 = 0; t2 < 2; t2++) {
            int col = nt0 + t2 * 8 + g;
            int k0 = ks * 8 + tt;
            float w0 = __ldg(&W1[k0 * 128 + col]);
            float w1 = __ldg(&W1[(k0 + 4) * 128 + col]);
            wh[ks][t2][0] = tf32_hi(w0); wl[ks][t2][0] = w0 - wh[ks][t2][0];
            wh[ks][t2][1] = tf32_hi(w1); wl[ks][t2][1] = w1 - wh[ks][t2][1];
        }
    float2 bias[2];
#pragma unroll
    for (int t2 = 0; t2 < 2; t2++)
        bias[t2] = *(const float2*)(b1 + nt0 + t2 * 8 + tt * 2);

    int srr = tid >> 4, sc4 = tid & 15;

    float sA[2][2] = {{0.f,0.f},{0.f,0.f}}, qA[2][2] = {{0.f,0.f},{0.f,0.f}};

    float4 pa = make_float4(0.f,0.f,0.f,0.f);
    int t = blockIdx.x;
    if (t < ntiles) {
        int row = t * 16 + srr;
        if (row < n) pa = ((const float4*)g_agg)[(size_t)row * 16 + sc4];
    }
    int buf = 0;
    for (; t < ntiles; t += gridDim.x) {
        {
            float* dh = &Zh[buf][srr][sc4 * 4];
            float* dl = &Zl[buf][srr][sc4 * 4];
            float h0 = tf32_hi(pa.x), h1 = tf32_hi(pa.y), h2 = tf32_hi(pa.z), h3 = tf32_hi(pa.w);
            dh[0] = h0; dh[1] = h1; dh[2] = h2; dh[3] = h3;
            dl[0] = pa.x - h0; dl[1] = pa.y - h1; dl[2] = pa.z - h2; dl[3] = pa.w - h3;
        }
        __syncthreads();

        int tn = t + gridDim.x;
        pa = make_float4(0.f,0.f,0.f,0.f);
        if (tn < ntiles) {
            int row = tn * 16 + srr;
            if (row < n) pa = ((const float4*)g_agg)[(size_t)row * 16 + sc4];
        }

        float acc[2][4] = {{0.f,0.f,0.f,0.f},{0.f,0.f,0.f,0.f}};
#pragma unroll
        for (int ks = 0; ks < 8; ks++) {
            int kc = ks * 8 + tt;
            float ah0 = Zh[buf][g][kc],     ah1 = Zh[buf][g + 8][kc];
            float ah2 = Zh[buf][g][kc + 4], ah3 = Zh[buf][g + 8][kc + 4];
            float al0 = Zl[buf][g][kc],     al1 = Zl[buf][g + 8][kc];
            float al2 = Zl[buf][g][kc + 4], al3 = Zl[buf][g + 8][kc + 4];
#pragma unroll
            for (int t2 = 0; t2 < 2; t2++) {
                mma8f(acc[t2], ah0, ah1, ah2, ah3, wh[ks][t2][0], wh[ks][t2][1]);
                mma8f(acc[t2], ah0, ah1, ah2, ah3, wl[ks][t2][0], wl[ks][t2][1]);
                mma8f(acc[t2], al0, al1, al2, al3, wh[ks][t2][0], wh[ks][t2][1]);
            }
        }

        int r0 = t * 16;
        int rA = r0 + g, rB = r0 + g + 8;
#pragma unroll
        for (int t2 = 0; t2 < 2; t2++) {
            int col = nt0 + t2 * 8 + tt * 2;
            float e0 = acc[t2][0] + bias[t2].x, o0 = acc[t2][1] + bias[t2].y;
            float e1 = acc[t2][2] + bias[t2].x, o1 = acc[t2][3] + bias[t2].y;
            if (rA < n) {
                *(float2*)(g_y1 + (size_t)rA * 128 + col) = make_float2(e0, o0);
                sA[t2][0] += e0; qA[t2][0] += e0 * e0;
                sA[t2][1] += o0; qA[t2][1] += o0 * o0;
            }
            if (rB < n) {
                *(float2*)(g_y1 + (size_t)rB * 128 + col) = make_float2(e1, o1);
                sA[t2][0] += e1; qA[t2][0] += e1 * e1;
                sA[t2][1] += o1; qA[t2][1] += o1 * o1;
            }
        }
        buf ^= 1;
    }

#pragma unroll
    for (int t2 = 0; t2 < 2; t2++)
#pragma unroll
        for (int j = 0; j < 2; j++) {
#pragma unroll
            for (int off = 4; off < 32; off <<= 1) {
                sA[t2][j] += __shfl_xor_sync(0xffffffffu, sA[t2][j], off);
                qA[t2][j] += __shfl_xor_sync(0xffffffffu, qA[t2][j], off);
            }
        }
    if (g == 0) {
#pragma unroll
        for (int t2 = 0; t2 < 2; t2++) {
            int col = nt0 + t2 * 8 + tt * 2;
            atomicAdd(&g_stats[col], sA[t2][0]);
            atomicAdd(&g_stats[col + 1], sA[t2][1]);
            atomicAdd(&g_stats[128 + col], qA[t2][0]);
            atomicAdd(&g_stats[128 + col + 1], qA[t2][1]);
        }
    }
}

// ---------------------------------------------------------------------------
// GEMM2 (tensor, B-stationary): t = relu(bn1(y1)) -> y2 = t@W2 + b2 -> g_agg.
// BN1 computed per block from g_stats. BN2 stats fused.
// ---------------------------------------------------------------------------
__global__ __launch_bounds__(256, 2) void gemm2_tc_kernel(
    const float* __restrict__ W2, const float* __restrict__ b2,
    const float* __restrict__ bn1_g, const float* __restrict__ bn1_b,
    float nInv, int n, int ntiles)
{
    __shared__ float Zh[2][16][132];
    __shared__ float Zl[2][16][132];
    __shared__ __align__(16) float bsc[128];
    __shared__ __align__(16) float bsh[128];

    int tid = threadIdx.x;
    int wid = tid >> 5;
    int lane = tid & 31;
    int g = lane >> 2, tt = lane & 3;
    int nt0 = wid * 8;

    if (tid < 128) {
        float mean = g_stats[tid] * nInv;
        float var = fmaxf(g_stats[128 + tid] * nInv - mean * mean, 0.f);
        float inv = rsqrtf(var + 1e-5f);
        float sc = __ldg(&bn1_g[tid]) * inv;
        bsc[tid] = sc;
        bsh[tid] = __ldg(&bn1_b[tid]) - mean * sc;
    }

    float wh[16][2], wl[16][2];
#pragma unroll
    for (int ks = 0; ks < 16; ks++) {
        int col = nt0 + g;
        int k0 = ks * 8 + tt;
        float w0 = __ldg(&W2[k0 * 64 + col]);
        float w1 = __ldg(&W2[(k0 + 4) * 64 + col]);
        wh[ks][0] = tf32_hi(w0); wl[ks][0] = w0 - wh[ks][0];
        wh[ks][1] = tf32_hi(w1); wl[ks][1] = w1 - wh[ks][1];
    }
    float2 bias = *(const float2*)(b2 + nt0 + tt * 2);

    int srr = tid >> 4, sc4b = (tid & 15) * 2;

    float sA[2] = {0.f, 0.f}, qA[2] = {0.f, 0.f};
    __syncthreads();

    float4 p0 = make_float4(0.f,0.f,0.f,0.f), p1 = p0;
    int t = blockIdx.x;
    if (t < ntiles) {
        int row = t * 16 + srr;
        if (row < n) {
            p0 = ((const float4*)g_y1)[(size_t)row * 32 + sc4b];
            p1 = ((const float4*)g_y1)[(size_t)row * 32 + sc4b + 1];
        }
    }
    int buf = 0;
    for (; t < ntiles; t += gridDim.x) {
        {
#pragma unroll
            for (int j = 0; j < 2; j++) {
                float4 y = j ? p1 : p0;
                int c4 = sc4b + j;
                float4 sc = ((const float4*)bsc)[c4];
                float4 sh = ((const float4*)bsh)[c4];
                float z0 = fmaxf(fmaf(y.x, sc.x, sh.x), 0.f);
                float z1 = fmaxf(fmaf(y.y, sc.y, sh.y), 0.f);
                float z2 = fmaxf(fmaf(y.z, sc.z, sh.z), 0.f);
                float z3 = fmaxf(fmaf(y.w, sc.w, sh.w), 0.f);
                float* dh = &Zh[buf][srr][c4 * 4];
                float* dl = &Zl[buf][srr][c4 * 4];
                float h0 = tf32_hi(z0), h1 = tf32_hi(z1), h2 = tf32_hi(z2), h3 = tf32_hi(z3);
                dh[0] = h0; dh[1] = h1; dh[2] = h2; dh[3] = h3;
                dl[0] = z0 - h0; dl[1] = z1 - h1; dl[2] = z2 - h2; dl[3] = z3 - h3;
            }
        }
        __syncthreads();

        int tn = t + gridDim.x;
        p0 = make_float4(0.f,0.f,0.f,0.f); p1 = p0;
        if (tn < ntiles) {
            int row = tn * 16 + srr;
            if (row < n) {
                p0 = ((const float4*)g_y1)[(size_t)row * 32 + sc4b];
                p1 = ((const float4*)g_y1)[(size_t)row * 32 + sc4b + 1];
            }
        }

        float acc[4] = {0.f, 0.f, 0.f, 0.f};
#pragma unroll
        for (int ks = 0; ks < 16; ks++) {
            int kc = ks * 8 + tt;
            float ah0 = Zh[buf][g][kc],     ah1 = Zh[buf][g + 8][kc];
            float ah2 = Zh[buf][g][kc + 4], ah3 = Zh[buf][g + 8][kc + 4];
            float al0 = Zl[buf][g][kc],     al1 = Zl[buf][g + 8][kc];
            float al2 = Zl[buf][g][kc + 4], al3 = Zl[buf][g + 8][kc + 4];
            mma8f(acc, ah0, ah1, ah2, ah3, wh[ks][0], wh[ks][1]);
            mma8f(acc, ah0, ah1, ah2, ah3, wl[ks][0], wl[ks][1]);
            mma8f(acc, al0, al1, al2, al3, wh[ks][0], wh[ks][1]);
        }

        int r0 = t * 16;
        int rA = r0 + g, rB = r0 + g + 8;
        int col = nt0 + tt * 2;
        float e0 = acc[0] + bias.x, o0 = acc[1] + bias.y;
        float e1 = acc[2] + bias.x, o1 = acc[3] + bias.y;
        if (rA < n) {
            *(float2*)(g_agg + (size_t)rA * 64 + col) = make_float2(e0, o0);
            sA[0] += e0; qA[0] += e0 * e0;
            sA[1] += o0; qA[1] += o0 * o0;
        }
        if (rB < n) {
            *(float2*)(g_agg + (size_t)rB * 64 + col) = make_float2(e1, o1);
            sA[0] += e1; qA[0] += e1 * e1;
            sA[1] += o1; qA[1] += o1 * o1;
        }
        buf ^= 1;
    }

#pragma unroll
    for (int j = 0; j < 2; j++) {
#pragma unroll
        for (int off = 4; off < 32; off <<= 1) {
            sA[j] += __shfl_xor_sync(0xffffffffu, sA[j], off);
            qA[j] += __shfl_xor_sync(0xffffffffu, qA[j], off);
        }
    }
    if (g == 0) {
        int col = nt0 + tt * 2;
        atomicAdd(&g_stats[256 + col], sA[0]);
        atomicAdd(&g_stats[256 + col + 1], sA[1]);
        atomicAdd(&g_stats[320 + col], qA[0]);
        atomicAdd(&g_stats[320 + col + 1], qA[1]);
    }
}

// ---------------------------------------------------------------------------
// BN2 apply. mode 0: relu -> g_h. mode 1: -> nodeout + fused pooling.
// ---------------------------------------------------------------------------
__global__ __launch_bounds__(256) void bn2_apply_kernel(
    const float* __restrict__ bn2_g, const float* __restrict__ bn2_b,
    float* __restrict__ nodeout, const int* __restrict__ batch,
    float* __restrict__ gout, float nInv, int n, int mode)
{
    __shared__ __align__(16) float bsc[64];
    __shared__ __align__(16) float bsh[64];
    if (threadIdx.x < 64) {
        int t = threadIdx.x;
        float mean = g_stats[256 + t] * nInv;
        float var = fmaxf(g_stats[320 + t] * nInv - mean * mean, 0.f);
        float inv = rsqrtf(var + 1e-5f);
        float sc = __ldg(&bn2_g[t]) * inv;
        bsc[t] = sc;
        bsh[t] = __ldg(&bn2_b[t]) - mean * sc;
    }
    __syncthreads();

    int i = blockIdx.x * 256 + threadIdx.x;
    if (i >= n * 16) return;
    int c = i & 15;
    float4 y = ((const float4*)g_agg)[i];
    float4 sc = ((const float4*)bsc)[c];
    float4 sh = ((const float4*)bsh)[c];
    float4 v;
    v.x = fmaf(y.x, sc.x, sh.x);
    v.y = fmaf(y.y, sc.y, sh.y);
    v.z = fmaf(y.z, sc.z, sh.z);
    v.w = fmaf(y.w, sc.w, sh.w);
    if (mode == 0) {
        v.x = fmaxf(v.x, 0.f); v.y = fmaxf(v.y, 0.f);
        v.z = fmaxf(v.z, 0.f); v.w = fmaxf(v.w, 0.f);
        ((float4*)g_h)[i] = v;
    } else {
        ((float4*)nodeout)[i] = v;
        int nid = i >> 4;
        int b = __ldg(&batch[nid]);
        red_add_v4(gout + (size_t)b * 64 + c * 4, v);
        if (c == 0) atomicAdd(&g_cnt[b], 1.0f);
    }
}

__global__ __launch_bounds__(256) void divide_kernel(float* __restrict__ gout, int b)
{
    int i = blockIdx.x * 256 + threadIdx.x;
    if (i < b * 64) gout[i] = gout[i] / (g_cnt[i >> 6] + 1e-9f);
}

// ---------------------------------------------------------------------------
// Launch
// ---------------------------------------------------------------------------
extern "C" void kernel_launch(void* const* d_in, const int* in_sizes, int n_in,
                              void* d_out, int out_size)
{
    const float* atom_emb = (const float*)d_in[0];
    const float* bond_emb = (const float*)d_in[1];
    const float* eps      = (const float*)d_in[2];
    const float* W1       = (const float*)d_in[3];
    const float* b1       = (const float*)d_in[4];
    const float* bn1_g    = (const float*)d_in[5];
    const float* bn1_b    = (const float*)d_in[6];
    const float* W2       = (const float*)d_in[7];
    const float* b2       = (const float*)d_in[8];
    const float* bn2_g    = (const float*)d_in[9];
    const float* bn2_b    = (const float*)d_in[10];
    const int* x_feat     = (const int*)d_in[11];
    const int* edge_index = (const int*)d_in[12];
    const int* edge_attr  = (const int*)d_in[13];
    const int* batch      = (const int*)d_in[14];

    int n = in_sizes[11] / 9;
    int e = in_sizes[12] / 2;
    int b = out_size / 64 - n;
    float* nodeout = (float*)d_out;
    float* gout = nodeout + (size_t)n * 64;

    int nodeGrid = (n * 16 + 255) / 256;
    int edgeBlocks = (e + 255) / 256;
    int scanBlocks = (n + 1023) / 1024;
    int ntiles = (n + 15) / 16;
    int gemmGrid = 296;
    int edgeGrid = 1036;
    float nInv = 1.0f / (float)n;

    atom_kernel<<<nodeGrid, 256>>>(atom_emb, x_feat, n);

    clear_off_kernel<<<(n + 256) / 256, 256>>>(n);
    hist_kernel<<<edgeBlocks, 256>>>(edge_index, e);
    scan_partial_kernel<<<scanBlocks, 1024>>>(n);
    scan_bsums_kernel<<<1, 32>>>(scanBlocks);
    scan_final_kernel<<<scanBlocks, 1024>>>(n);
    copy_cur_kernel<<<(n + 255) / 256, 256>>>(n);
    scatter_kernel<<<edgeBlocks, 256>>>(edge_index, edge_attr, e);

    clear_pool_kernel<<<(b * 64 + 255) / 256, 256>>>(gout, b);

    for (int l = 0; l < 4; l++) {
        edge_csr_kernel<<<edgeGrid, 256>>>(bond_emb + l * 1536, eps + l, n);
        gemm1_tc_kernel<<<gemmGrid, 256>>>(W1 + l * 64 * 128, b1 + l * 128, n, ntiles);
        gemm2_tc_kernel<<<gemmGrid, 256>>>(W2 + l * 128 * 64, b2 + l * 64,
                                           bn1_g + l * 128, bn1_b + l * 128, nInv, n, ntiles);
        bn2_apply_kernel<<<nodeGrid, 256>>>(bn2_g + l * 64, bn2_b + l * 64,
                                            nodeout, batch, gout, nInv, n, (l == 3) ? 1 : 0);
    }

    divide_kernel<<<(b * 64 + 255) / 256, 256>>>(gout, b);
}

// round 15
// speedup vs baseline: 1.0569x; 1.0569x over previous
#include <cuda_runtime.h>
#include <cstdint>

// ---------------------------------------------------------------------------
// GIN graph network, fp32. N=100000, E=1.25M, D=64, L=4, B=2048.
// R11 structure: CSR-by-dst edge aggregation (warp-per-node, unroll-2 with
// meta-load software pipelining), B-stationary mma.sync tf32 3-pass GEMMs,
// separate bn2_apply.
// ---------------------------------------------------------------------------

#define MAXN 100000
#define MAXE 1250000
#define MAXB 2048

__device__ __align__(16) float g_h[(size_t)MAXN * 64];
__device__ __align__(16) float g_agg[(size_t)MAXN * 64];   // z buffer / y2 buffer
__device__ __align__(16) float g_y1[(size_t)MAXN * 128];
__device__ __align__(16) float g_stats[384];  // [0:128) sum1 [128:256) sq1 [256:320) sum2 [320:384) sq2
__device__ float g_cnt[MAXB];
__device__ int g_off[MAXN + 1];
__device__ int g_cur[MAXN];
__device__ int g_bsum[128];
__device__ __align__(8) int2 g_csr[MAXE];     // (src, combo) grouped by dst

__device__ __forceinline__ void red_add_v4(float* addr, float4 v) {
    asm volatile("red.global.add.v4.f32 [%0], {%1,%2,%3,%4};"
                 :: "l"(addr), "f"(v.x), "f"(v.y), "f"(v.z), "f"(v.w)
                 : "memory");
}

__device__ __forceinline__ float tf32_hi(float x) {
    return __uint_as_float(__float_as_uint(x) & 0xFFFFE000u);
}

__device__ __forceinline__ void mma8f(float* d, float a0, float a1, float a2, float a3,
                                      float b0, float b1) {
    asm volatile(
        "mma.sync.aligned.m16n8k8.row.col.f32.tf32.tf32.f32 "
        "{%0,%1,%2,%3}, {%4,%5,%6,%7}, {%8,%9}, {%0,%1,%2,%3};"
        : "+f"(d[0]), "+f"(d[1]), "+f"(d[2]), "+f"(d[3])
        : "r"(__float_as_uint(a0)), "r"(__float_as_uint(a1)),
          "r"(__float_as_uint(a2)), "r"(__float_as_uint(a3)),
          "r"(__float_as_uint(b0)), "r"(__float_as_uint(b1)));
}

// ---------------------------------------------------------------------------
// Atom encoder
// ---------------------------------------------------------------------------
__global__ __launch_bounds__(256) void atom_kernel(
    const float* __restrict__ atom_emb, const int* __restrict__ x_feat, int n)
{
    int wi = blockIdx.x * 256 + threadIdx.x;
    int nid = wi >> 4;
    if (nid >= n) return;
    int c = wi & 15;
    const float4* ae = (const float4*)atom_emb;
    float4 acc = make_float4(0.f, 0.f, 0.f, 0.f);
#pragma unroll
    for (int f = 0; f < 9; f++) {
        int idx = __ldg(&x_feat[nid * 9 + f]);
        float4 v = ae[(f * 128 + idx) * 16 + c];
        acc.x += v.x; acc.y += v.y; acc.z += v.z; acc.w += v.w;
    }
    ((float4*)g_h)[(size_t)nid * 16 + c] = acc;
}

// ---------------------------------------------------------------------------
// CSR build (one-time): histogram -> scan -> scatter
// ---------------------------------------------------------------------------
__global__ __launch_bounds__(256) void clear_off_kernel(int n)
{
    int i = blockIdx.x * 256 + threadIdx.x;
    if (i <= n) g_off[i] = 0;
    if (i == 0) g_cur[0] = 0;
}

__global__ __launch_bounds__(256) void hist_kernel(
    const int* __restrict__ edge_index, int e)
{
    int i = blockIdx.x * 256 + threadIdx.x;
    if (i >= e) return;
    atomicAdd(&g_off[__ldg(&edge_index[e + i]) + 1], 1);
}

__global__ __launch_bounds__(1024) void scan_partial_kernel(int n)
{
    int tid = threadIdx.x;
    int j = 1 + blockIdx.x * 1024 + tid;
    int v = (j <= n) ? g_off[j] : 0;
    __shared__ int ws[32];
    int lane = tid & 31, w = tid >> 5;
#pragma unroll
    for (int off = 16; off > 0; off >>= 1) v += __shfl_down_sync(0xffffffffu, v, off);
    if (lane == 0) ws[w] = v;
    __syncthreads();
    if (w == 0) {
        int t = ws[lane];
#pragma unroll
        for (int off = 16; off > 0; off >>= 1) t += __shfl_down_sync(0xffffffffu, t, off);
        if (lane == 0) g_bsum[blockIdx.x] = t;
    }
}

__global__ void scan_bsums_kernel(int nblocks)
{
    if (threadIdx.x == 0) {
        int carry = 0;
        for (int b = 0; b < nblocks; b++) {
            int t = g_bsum[b];
            g_bsum[b] = carry;
            carry += t;
        }
    }
}

__global__ __launch_bounds__(1024) void scan_final_kernel(int n)
{
    int tid = threadIdx.x;
    int j = 1 + blockIdx.x * 1024 + tid;
    int v = (j <= n) ? g_off[j] : 0;
    __shared__ int ws[32];
    int lane = tid & 31, w = tid >> 5;
    int x = v;
#pragma unroll
    for (int off = 1; off < 32; off <<= 1) {
        int t = __shfl_up_sync(0xffffffffu, x, off);
        if (lane >= off) x += t;
    }
    if (lane == 31) ws[w] = x;
    __syncthreads();
    if (w == 0) {
        int t = ws[lane];
#pragma unroll
        for (int off = 1; off < 32; off <<= 1) {
            int u = __shfl_up_sync(0xffffffffu, t, off);
            if (lane >= off) t += u;
        }
        ws[lane] = t;
    }
    __syncthreads();
    int pref = (w > 0) ? ws[w - 1] : 0;
    if (j <= n) {
        int val = x + pref + g_bsum[blockIdx.x];
        g_off[j] = val;
        if (j < n) g_cur[j] = val;   // fold copy_cur here
    }
}

__global__ __launch_bounds__(256) void scatter_kernel(
    const int* __restrict__ edge_index, const int* __restrict__ edge_attr, int e)
{
    int i = blockIdx.x * 256 + threadIdx.x;
    if (i >= e) return;
    int src = __ldg(&edge_index[i]);
    int dst = __ldg(&edge_index[e + i]);
    int a0 = __ldg(&edge_attr[3 * i + 0]);
    int a1 = __ldg(&edge_attr[3 * i + 1]);
    int a2 = __ldg(&edge_attr[3 * i + 2]);
    int pos = atomicAdd(&g_cur[dst], 1);
    g_csr[pos] = make_int2(src, a0 * 25 + a1 * 5 + a2);
}

__global__ __launch_bounds__(256) void clear_pool_kernel(float* __restrict__ gout, int b)
{
    int i = blockIdx.x * 256 + threadIdx.x;
    if (i < b * 64) gout[i] = 0.f;
    if (i < b) g_cnt[i] = 0.f;
}

// ---------------------------------------------------------------------------
// Edge kernel (CSR): warp-per-node, unroll-2 with meta prefetch (software
// pipelining breaks the csr->h serial latency chain). lane = float2 chunk.
// z = (1+eps)*h[nid] + sum relu(h[src] + table[combo]) -> g_agg.
// Block 0 zeroes g_stats.
// ---------------------------------------------------------------------------
__global__ __launch_bounds__(256) void edge_csr_kernel(
    const float* __restrict__ bond_emb_l, const float* __restrict__ epsp, int n)
{
    __shared__ __align__(16) float table[125 * 64];   // 31.25 KB

    if (blockIdx.x == 0 && threadIdx.x < 128) {
        g_stats[threadIdx.x] = 0.f;
        g_stats[128 + threadIdx.x] = 0.f;
        g_stats[256 + threadIdx.x] = 0.f;
    }

    const float4* b4 = (const float4*)bond_emb_l;     // [3,8,16] float4
    for (int t = threadIdx.x; t < 2000; t += 256) {
        int combo = t >> 4, c4 = t & 15;
        int a0 = combo / 25;
        int rr = combo - a0 * 25;
        int a1 = rr / 5;
        int a2 = rr - a1 * 5;
        float4 v0 = b4[a0 * 16 + c4];
        float4 v1 = b4[(8 + a1) * 16 + c4];
        float4 v2 = b4[(16 + a2) * 16 + c4];
        float4 s;
        s.x = v0.x + v1.x + v2.x;
        s.y = v0.y + v1.y + v2.y;
        s.z = v0.z + v1.z + v2.z;
        s.w = v0.w + v1.w + v2.w;
        ((float4*)table)[t] = s;
    }
    __syncthreads();

    float epsv = 1.0f + __ldg(epsp);
    int lane = threadIdx.x & 31;
    int w = threadIdx.x >> 5;
    const float2* th2 = (const float2*)table;
    const float2* h2 = (const float2*)g_h;

    for (int nid = blockIdx.x * 8 + w; nid < n; nid += gridDim.x * 8) {
        int s = __ldg(&g_off[nid]);
        int epos = __ldg(&g_off[nid + 1]);
        float2 a0 = make_float2(0.f, 0.f), a1 = make_float2(0.f, 0.f);
        int j = s;
        int2 m0, m1;
        if (j + 2 <= epos) {
            m0 = __ldg(&g_csr[j]);
            m1 = __ldg(&g_csr[j + 1]);
        }
        while (j + 2 <= epos) {
            int2 c0 = m0, c1 = m1;
            int jn = j + 2;
            if (jn + 2 <= epos) {
                m0 = __ldg(&g_csr[jn]);
                m1 = __ldg(&g_csr[jn + 1]);
            }
            float2 h0 = h2[(size_t)c0.x * 32 + lane];
            float2 h1 = h2[(size_t)c1.x * 32 + lane];
            float2 e0 = th2[c0.y * 32 + lane];
            float2 e1 = th2[c1.y * 32 + lane];
            a0.x += fmaxf(h0.x + e0.x, 0.f);
            a0.y += fmaxf(h0.y + e0.y, 0.f);
            a1.x += fmaxf(h1.x + e1.x, 0.f);
            a1.y += fmaxf(h1.y + e1.y, 0.f);
            j = jn;
        }
        if (j < epos) {
            int2 mm = __ldg(&g_csr[j]);
            float2 h0 = h2[(size_t)mm.x * 32 + lane];
            float2 e0 = th2[mm.y * 32 + lane];
            a0.x += fmaxf(h0.x + e0.x, 0.f);
            a0.y += fmaxf(h0.y + e0.y, 0.f);
        }
        float2 hd = h2[(size_t)nid * 32 + lane];
        float2 z;
        z.x = fmaf(epsv, hd.x, a0.x + a1.x);
        z.y = fmaf(epsv, hd.y, a0.y + a1.y);
        ((float2*)g_agg)[(size_t)nid * 32 + lane] = z;
    }
}

// ---------------------------------------------------------------------------
// GEMM1 (tensor, B-stationary): z (g_agg) -> y1 = z@W1+b1 (g_y1). Fused BN1
// stats.
// ---------------------------------------------------------------------------
__global__ __launch_bounds__(256, 2) void gemm1_tc_kernel(
    const float* __restrict__ W1, const float* __restrict__ b1, int n, int ntiles)
{
    __shared__ float Zh[2][16][68];
    __shared__ float Zl[2][16][68];

    int tid = threadIdx.x;
    int wid = tid >> 5;
    int lane = tid & 31;
    int g = lane >> 2, tt = lane & 3;
    int nt0 = wid * 16;

    float wh[8][2][2], wl[8][2][2];
#pragma unroll
    for (int ks = 0; ks < 8; ks++)
#pragma unroll
        for (int t2 = 0; t2 < 2; t2++) {
            int col = nt0 + t2 * 8 + g;
            int k0 = ks * 8 + tt;
            float w0 = __ldg(&W1[k0 * 128 + col]);
            float w1 = __ldg(&W1[(k0 + 4) * 128 + col]);
            wh[ks][t2][0] = tf32_hi(w0); wl[ks][t2][0] = w0 - wh[ks][t2][0];
            wh[ks][t2][1] = tf32_hi(w1); wl[ks][t2][1] = w1 - wh[ks][t2][1];
        }
    float2 bias[2];
#pragma unroll
    for (int t2 = 0; t2 < 2; t2++)
        bias[t2] = *(const float2*)(b1 + nt0 + t2 * 8 + tt * 2);

    int srr = tid >> 4, sc4 = tid & 15;

    float sA[2][2] = {{0.f,0.f},{0.f,0.f}}, qA[2][2] = {{0.f,0.f},{0.f,0.f}};

    float4 pa = make_float4(0.f,0.f,0.f,0.f);
    int t = blockIdx.x;
    if (t < ntiles) {
        int row = t * 16 + srr;
        if (row < n) pa = ((const float4*)g_agg)[(size_t)row * 16 + sc4];
    }
    int buf = 0;
    for (; t < ntiles; t += gridDim.x) {
        {
            float* dh = &Zh[buf][srr][sc4 * 4];
            float* dl = &Zl[buf][srr][sc4 * 4];
            float h0 = tf32_hi(pa.x), h1 = tf32_hi(pa.y), h2 = tf32_hi(pa.z), h3 = tf32_hi(pa.w);
            dh[0] = h0; dh[1] = h1; dh[2] = h2; dh[3] = h3;
            dl[0] = pa.x - h0; dl[1] = pa.y - h1; dl[2] = pa.z - h2; dl[3] = pa.w - h3;
        }
        __syncthreads();

        int tn = t + gridDim.x;
        pa = make_float4(0.f,0.f,0.f,0.f);
        if (tn < ntiles) {
            int row = tn * 16 + srr;
            if (row < n) pa = ((const float4*)g_agg)[(size_t)row * 16 + sc4];
        }

        float acc[2][4] = {{0.f,0.f,0.f,0.f},{0.f,0.f,0.f,0.f}};
#pragma unroll
        for (int ks = 0; ks < 8; ks++) {
            int kc = ks * 8 + tt;
            float ah0 = Zh[buf][g][kc],     ah1 = Zh[buf][g + 8][kc];
            float ah2 = Zh[buf][g][kc + 4], ah3 = Zh[buf][g + 8][kc + 4];
            float al0 = Zl[buf][g][kc],     al1 = Zl[buf][g + 8][kc];
            float al2 = Zl[buf][g][kc + 4], al3 = Zl[buf][g + 8][kc + 4];
#pragma unroll
            for (int t2 = 0; t2 < 2; t2++) {
                mma8f(acc[t2], ah0, ah1, ah2, ah3, wh[ks][t2][0], wh[ks][t2][1]);
                mma8f(acc[t2], ah0, ah1, ah2, ah3, wl[ks][t2][0], wl[ks][t2][1]);
                mma8f(acc[t2], al0, al1, al2, al3, wh[ks][t2][0], wh[ks][t2][1]);
            }
        }

        int r0 = t * 16;
        int rA = r0 + g, rB = r0 + g + 8;
#pragma unroll
        for (int t2 = 0; t2 < 2; t2++) {
            int col = nt0 + t2 * 8 + tt * 2;
            float e0 = acc[t2][0] + bias[t2].x, o0 = acc[t2][1] + bias[t2].y;
            float e1 = acc[t2][2] + bias[t2].x, o1 = acc[t2][3] + bias[t2].y;
            if (rA < n) {
                *(float2*)(g_y1 + (size_t)rA * 128 + col) = make_float2(e0, o0);
                sA[t2][0] += e0; qA[t2][0] += e0 * e0;
                sA[t2][1] += o0; qA[t2][1] += o0 * o0;
            }
            if (rB < n) {
                *(float2*)(g_y1 + (size_t)rB * 128 + col) = make_float2(e1, o1);
                sA[t2][0] += e1; qA[t2][0] += e1 * e1;
                sA[t2][1] += o1; qA[t2][1] += o1 * o1;
            }
        }
        buf ^= 1;
    }

#pragma unroll
    for (int t2 = 0; t2 < 2; t2++)
#pragma unroll
        for (int j = 0; j < 2; j++) {
#pragma unroll
            for (int off = 4; off < 32; off <<= 1) {
                sA[t2][j] += __shfl_xor_sync(0xffffffffu, sA[t2][j], off);
                qA[t2][j] += __shfl_xor_sync(0xffffffffu, qA[t2][j], off);
            }
        }
    if (g == 0) {
#pragma unroll
        for (int t2 = 0; t2 < 2; t2++) {
            int col = nt0 + t2 * 8 + tt * 2;
            atomicAdd(&g_stats[col], sA[t2][0]);
            atomicAdd(&g_stats[col + 1], sA[t2][1]);
            atomicAdd(&g_stats[128 + col], qA[t2][0]);
            atomicAdd(&g_stats[128 + col + 1], qA[t2][1]);
        }
    }
}

// ---------------------------------------------------------------------------
// GEMM2 (tensor, B-stationary): t = relu(bn1(y1)) -> y2 = t@W2 + b2 -> g_agg.
// BN1 computed per block from g_stats. BN2 stats fused.
// ---------------------------------------------------------------------------
__global__ __launch_bounds__(256, 2) void gemm2_tc_kernel(
    const float* __restrict__ W2, const float* __restrict__ b2,
    const float* __restrict__ bn1_g, const float* __restrict__ bn1_b,
    float nInv, int n, int ntiles)
{
    __shared__ float Zh[2][16][132];
    __shared__ float Zl[2][16][132];
    __shared__ __align__(16) float bsc[128];
    __shared__ __align__(16) float bsh[128];

    int tid = threadIdx.x;
    int wid = tid >> 5;
    int lane = tid & 31;
    int g = lane >> 2, tt = lane & 3;
    int nt0 = wid * 8;

    if (tid < 128) {
        float mean = g_stats[tid] * nInv;
        float var = fmaxf(g_stats[128 + tid] * nInv - mean * mean, 0.f);
        float inv = rsqrtf(var + 1e-5f);
        float sc = __ldg(&bn1_g[tid]) * inv;
        bsc[tid] = sc;
        bsh[tid] = __ldg(&bn1_b[tid]) - mean * sc;
    }

    float wh[16][2], wl[16][2];
#pragma unroll
    for (int ks = 0; ks < 16; ks++) {
        int col = nt0 + g;
        int k0 = ks * 8 + tt;
        float w0 = __ldg(&W2[k0 * 64 + col]);
        float w1 = __ldg(&W2[(k0 + 4) * 64 + col]);
        wh[ks][0] = tf32_hi(w0); wl[ks][0] = w0 - wh[ks][0];
        wh[ks][1] = tf32_hi(w1); wl[ks][1] = w1 - wh[ks][1];
    }
    float2 bias = *(const float2*)(b2 + nt0 + tt * 2);

    int srr = tid >> 4, sc4b = (tid & 15) * 2;

    float sA[2] = {0.f, 0.f}, qA[2] = {0.f, 0.f};
    __syncthreads();

    float4 p0 = make_float4(0.f,0.f,0.f,0.f), p1 = p0;
    int t = blockIdx.x;
    if (t < ntiles) {
        int row = t * 16 + srr;
        if (row < n) {
            p0 = ((const float4*)g_y1)[(size_t)row * 32 + sc4b];
            p1 = ((const float4*)g_y1)[(size_t)row * 32 + sc4b + 1];
        }
    }
    int buf = 0;
    for (; t < ntiles; t += gridDim.x) {
        {
#pragma unroll
            for (int j = 0; j < 2; j++) {
                float4 y = j ? p1 : p0;
                int c4 = sc4b + j;
                float4 sc = ((const float4*)bsc)[c4];
                float4 sh = ((const float4*)bsh)[c4];
                float z0 = fmaxf(fmaf(y.x, sc.x, sh.x), 0.f);
                float z1 = fmaxf(fmaf(y.y, sc.y, sh.y), 0.f);
                float z2 = fmaxf(fmaf(y.z, sc.z, sh.z), 0.f);
                float z3 = fmaxf(fmaf(y.w, sc.w, sh.w), 0.f);
                float* dh = &Zh[buf][srr][c4 * 4];
                float* dl = &Zl[buf][srr][c4 * 4];
                float h0 = tf32_hi(z0), h1 = tf32_hi(z1), h2 = tf32_hi(z2), h3 = tf32_hi(z3);
                dh[0] = h0; dh[1] = h1; dh[2] = h2; dh[3] = h3;
                dl[0] = z0 - h0; dl[1] = z1 - h1; dl[2] = z2 - h2; dl[3] = z3 - h3;
            }
        }
        __syncthreads();

        int tn = t + gridDim.x;
        p0 = make_float4(0.f,0.f,0.f,0.f); p1 = p0;
        if (tn < ntiles) {
            int row = tn * 16 + srr;
            if (row < n) {
                p0 = ((const float4*)g_y1)[(size_t)row * 32 + sc4b];
                p1 = ((const float4*)g_y1)[(size_t)row * 32 + sc4b + 1];
            }
        }

        float acc[4] = {0.f, 0.f, 0.f, 0.f};
#pragma unroll
        for (int ks = 0; ks < 16; ks++) {
            int kc = ks * 8 + tt;
            float ah0 = Zh[buf][g][kc],     ah1 = Zh[buf][g + 8][kc];
            float ah2 = Zh[buf][g][kc + 4], ah3 = Zh[buf][g + 8][kc + 4];
            float al0 = Zl[buf][g][kc],     al1 = Zl[buf][g + 8][kc];
            float al2 = Zl[buf][g][kc + 4], al3 = Zl[buf][g + 8][kc + 4];
            mma8f(acc, ah0, ah1, ah2, ah3, wh[ks][0], wh[ks][1]);
            mma8f(acc, ah0, ah1, ah2, ah3, wl[ks][0], wl[ks][1]);
            mma8f(acc, al0, al1, al2, al3, wh[ks][0], wh[ks][1]);
        }

        int r0 = t * 16;
        int rA = r0 + g, rB = r0 + g + 8;
        int col = nt0 + tt * 2;
        float e0 = acc[0] + bias.x, o0 = acc[1] + bias.y;
        float e1 = acc[2] + bias.x, o1 = acc[3] + bias.y;
        if (rA < n) {
            *(float2*)(g_agg + (size_t)rA * 64 + col) = make_float2(e0, o0);
            sA[0] += e0; qA[0] += e0 * e0;
            sA[1] += o0; qA[1] += o0 * o0;
        }
        if (rB < n) {
            *(float2*)(g_agg + (size_t)rB * 64 + col) = make_float2(e1, o1);
            sA[0] += e1; qA[0] += e1 * e1;
            sA[1] += o1; qA[1] += o1 * o1;
        }
        buf ^= 1;
    }

#pragma unroll
    for (int j = 0; j < 2; j++) {
#pragma unroll
        for (int off = 4; off < 32; off <<= 1) {
            sA[j] += __shfl_xor_sync(0xffffffffu, sA[j], off);
            qA[j] += __shfl_xor_sync(0xffffffffu, qA[j], off);
        }
    }
    if (g == 0) {
        int col = nt0 + tt * 2;
        atomicAdd(&g_stats[256 + col], sA[0]);
        atomicAdd(&g_stats[256 + col + 1], sA[1]);
        atomicAdd(&g_stats[320 + col], qA[0]);
        atomicAdd(&g_stats[320 + col + 1], qA[1]);
    }
}

// ---------------------------------------------------------------------------
// BN2 apply. mode 0: relu -> g_h. mode 1: -> nodeout + fused pooling.
// ---------------------------------------------------------------------------
__global__ __launch_bounds__(256) void bn2_apply_kernel(
    const float* __restrict__ bn2_g, const float* __restrict__ bn2_b,
    float* __restrict__ nodeout, const int* __restrict__ batch,
    float* __restrict__ gout, float nInv, int n, int mode)
{
    __shared__ __align__(16) float bsc[64];
    __shared__ __align__(16) float bsh[64];
    if (threadIdx.x < 64) {
        int t = threadIdx.x;
        float mean = g_stats[256 + t] * nInv;
        float var = fmaxf(g_stats[320 + t] * nInv - mean * mean, 0.f);
        float inv = rsqrtf(var + 1e-5f);
        float sc = __ldg(&bn2_g[t]) * inv;
        bsc[t] = sc;
        bsh[t] = __ldg(&bn2_b[t]) - mean * sc;
    }
    __syncthreads();

    int i = blockIdx.x * 256 + threadIdx.x;
    if (i >= n * 16) return;
    int c = i & 15;
    float4 y = ((const float4*)g_agg)[i];
    float4 sc = ((const float4*)bsc)[c];
    float4 sh = ((const float4*)bsh)[c];
    float4 v;
    v.x = fmaf(y.x, sc.x, sh.x);
    v.y = fmaf(y.y, sc.y, sh.y);
    v.z = fmaf(y.z, sc.z, sh.z);
    v.w = fmaf(y.w, sc.w, sh.w);
    if (mode == 0) {
        v.x = fmaxf(v.x, 0.f); v.y = fmaxf(v.y, 0.f);
        v.z = fmaxf(v.z, 0.f); v.w = fmaxf(v.w, 0.f);
        ((float4*)g_h)[i] = v;
    } else {
        ((float4*)nodeout)[i] = v;
        int nid = i >> 4;
        int b = __ldg(&batch[nid]);
        red_add_v4(gout + (size_t)b * 64 + c * 4, v);
        if (c == 0) atomicAdd(&g_cnt[b], 1.0f);
    }
}

__global__ __launch_bounds__(256) void divide_kernel(float* __restrict__ gout, int b)
{
    int i = blockIdx.x * 256 + threadIdx.x;
    if (i < b * 64) gout[i] = gout[i] / (g_cnt[i >> 6] + 1e-9f);
}

// ---------------------------------------------------------------------------
// Launch
// ---------------------------------------------------------------------------
extern "C" void kernel_launch(void* const* d_in, const int* in_sizes, int n_in,
                              void* d_out, int out_size)
{
    const float* atom_emb = (const float*)d_in[0];
    const float* bond_emb = (const float*)d_in[1];
    const float* eps      = (const float*)d_in[2];
    const float* W1       = (const float*)d_in[3];
    const float* b1       = (const float*)d_in[4];
    const float* bn1_g    = (const float*)d_in[5];
    const float* bn1_b    = (const float*)d_in[6];
    const float* W2       = (const float*)d_in[7];
    const float* b2       = (const float*)d_in[8];
    const float* bn2_g    = (const float*)d_in[9];
    const float* bn2_b    = (const float*)d_in[10];
    const int* x_feat     = (const int*)d_in[11];
    const int* edge_index = (const int*)d_in[12];
    const int* edge_attr  = (const int*)d_in[13];
    const int* batch      = (const int*)d_in[14];

    int n = in_sizes[11] / 9;
    int e = in_sizes[12] / 2;
    int b = out_size / 64 - n;
    float* nodeout = (float*)d_out;
    float* gout = nodeout + (size_t)n * 64;

    int nodeGrid = (n * 16 + 255) / 256;
    int edgeBlocks = (e + 255) / 256;
    int scanBlocks = (n + 1023) / 1024;
    int ntiles = (n + 15) / 16;
    int gemmGrid = 296;
    int edgeGrid = 1036;
    float nInv = 1.0f / (float)n;

    atom_kernel<<<nodeGrid, 256>>>(atom_emb, x_feat, n);

    clear_off_kernel<<<(n + 256) / 256, 256>>>(n);
    hist_kernel<<<edgeBlocks, 256>>>(edge_index, e);
    scan_partial_kernel<<<scanBlocks, 1024>>>(n);
    scan_bsums_kernel<<<1, 32>>>(scanBlocks);
    scan_final_kernel<<<scanBlocks, 1024>>>(n);
    scatter_kernel<<<edgeBlocks, 256>>>(edge_index, edge_attr, e);

    clear_pool_kernel<<<(b * 64 + 255) / 256, 256>>>(gout, b);

    for (int l = 0; l < 4; l++) {
        edge_csr_kernel<<<edgeGrid, 256>>>(bond_emb + l * 1536, eps + l, n);
        gemm1_tc_kernel<<<gemmGrid, 256>>>(W1 + l * 64 * 128, b1 + l * 128, n, ntiles);
        gemm2_tc_kernel<<<gemmGrid, 256>>>(W2 + l * 128 * 64, b2 + l * 64,
                                           bn1_g + l * 128, bn1_b + l * 128, nInv, n, ntiles);
        bn2_apply_kernel<<<nodeGrid, 256>>>(bn2_g + l * 64, bn2_b + l * 64,
                                            nodeout, batch, gout, nInv, n, (l == 3) ? 1 : 0);
    }

    divide_kernel<<<(b * 64 + 255) / 256, 256>>>(gout, b);
}

// round 16
// speedup vs baseline: 1.1210x; 1.0606x over previous
#include <cuda_runtime.h>
#include <cstdint>

// ---------------------------------------------------------------------------
// GIN graph network, fp32. N=100000, E=1.25M, D=64, L=4, B=2048.
// R11 structure: CSR-by-dst edge aggregation (warp-per-node, unroll-2),
// 512-thread edge blocks for 100% occupancy, B-stationary mma.sync tf32
// 3-pass GEMMs, separate bn2_apply.
// ---------------------------------------------------------------------------

#define MAXN 100000
#define MAXE 1250000
#define MAXB 2048

__device__ __align__(16) float g_h[(size_t)MAXN * 64];
__device__ __align__(16) float g_agg[(size_t)MAXN * 64];   // z buffer / y2 buffer
__device__ __align__(16) float g_y1[(size_t)MAXN * 128];
__device__ __align__(16) float g_stats[384];  // [0:128) sum1 [128:256) sq1 [256:320) sum2 [320:384) sq2
__device__ float g_cnt[MAXB];
__device__ int g_off[MAXN + 1];
__device__ int g_cur[MAXN];
__device__ int g_bsum[128];
__device__ __align__(8) int2 g_csr[MAXE];     // (src, combo) grouped by dst

__device__ __forceinline__ void red_add_v4(float* addr, float4 v) {
    asm volatile("red.global.add.v4.f32 [%0], {%1,%2,%3,%4};"
                 :: "l"(addr), "f"(v.x), "f"(v.y), "f"(v.z), "f"(v.w)
                 : "memory");
}

__device__ __forceinline__ float tf32_hi(float x) {
    return __uint_as_float(__float_as_uint(x) & 0xFFFFE000u);
}

__device__ __forceinline__ void mma8f(float* d, float a0, float a1, float a2, float a3,
                                      float b0, float b1) {
    asm volatile(
        "mma.sync.aligned.m16n8k8.row.col.f32.tf32.tf32.f32 "
        "{%0,%1,%2,%3}, {%4,%5,%6,%7}, {%8,%9}, {%0,%1,%2,%3};"
        : "+f"(d[0]), "+f"(d[1]), "+f"(d[2]), "+f"(d[3])
        : "r"(__float_as_uint(a0)), "r"(__float_as_uint(a1)),
          "r"(__float_as_uint(a2)), "r"(__float_as_uint(a3)),
          "r"(__float_as_uint(b0)), "r"(__float_as_uint(b1)));
}

// ---------------------------------------------------------------------------
// Atom encoder
// ---------------------------------------------------------------------------
__global__ __launch_bounds__(256) void atom_kernel(
    const float* __restrict__ atom_emb, const int* __restrict__ x_feat, int n)
{
    int wi = blockIdx.x * 256 + threadIdx.x;
    int nid = wi >> 4;
    if (nid >= n) return;
    int c = wi & 15;
    const float4* ae = (const float4*)atom_emb;
    float4 acc = make_float4(0.f, 0.f, 0.f, 0.f);
#pragma unroll
    for (int f = 0; f < 9; f++) {
        int idx = __ldg(&x_feat[nid * 9 + f]);
        float4 v = ae[(f * 128 + idx) * 16 + c];
        acc.x += v.x; acc.y += v.y; acc.z += v.z; acc.w += v.w;
    }
    ((float4*)g_h)[(size_t)nid * 16 + c] = acc;
}

// ---------------------------------------------------------------------------
// CSR build (one-time): histogram -> scan -> scatter
// ---------------------------------------------------------------------------
__global__ __launch_bounds__(256) void clear_off_kernel(int n)
{
    int i = blockIdx.x * 256 + threadIdx.x;
    if (i <= n) g_off[i] = 0;
    if (i == 0) g_cur[0] = 0;
}

__global__ __launch_bounds__(256) void hist_kernel(
    const int* __restrict__ edge_index, int e)
{
    int i = blockIdx.x * 256 + threadIdx.x;
    if (i >= e) return;
    atomicAdd(&g_off[__ldg(&edge_index[e + i]) + 1], 1);
}

__global__ __launch_bounds__(1024) void scan_partial_kernel(int n)
{
    int tid = threadIdx.x;
    int j = 1 + blockIdx.x * 1024 + tid;
    int v = (j <= n) ? g_off[j] : 0;
    __shared__ int ws[32];
    int lane = tid & 31, w = tid >> 5;
#pragma unroll
    for (int off = 16; off > 0; off >>= 1) v += __shfl_down_sync(0xffffffffu, v, off);
    if (lane == 0) ws[w] = v;
    __syncthreads();
    if (w == 0) {
        int t = ws[lane];
#pragma unroll
        for (int off = 16; off > 0; off >>= 1) t += __shfl_down_sync(0xffffffffu, t, off);
        if (lane == 0) g_bsum[blockIdx.x] = t;
    }
}

__global__ void scan_bsums_kernel(int nblocks)
{
    if (threadIdx.x == 0) {
        int carry = 0;
        for (int b = 0; b < nblocks; b++) {
            int t = g_bsum[b];
            g_bsum[b] = carry;
            carry += t;
        }
    }
}

__global__ __launch_bounds__(1024) void scan_final_kernel(int n)
{
    int tid = threadIdx.x;
    int j = 1 + blockIdx.x * 1024 + tid;
    int v = (j <= n) ? g_off[j] : 0;
    __shared__ int ws[32];
    int lane = tid & 31, w = tid >> 5;
    int x = v;
#pragma unroll
    for (int off = 1; off < 32; off <<= 1) {
        int t = __shfl_up_sync(0xffffffffu, x, off);
        if (lane >= off) x += t;
    }
    if (lane == 31) ws[w] = x;
    __syncthreads();
    if (w == 0) {
        int t = ws[lane];
#pragma unroll
        for (int off = 1; off < 32; off <<= 1) {
            int u = __shfl_up_sync(0xffffffffu, t, off);
            if (lane >= off) t += u;
        }
        ws[lane] = t;
    }
    __syncthreads();
    int pref = (w > 0) ? ws[w - 1] : 0;
    if (j <= n) {
        int val = x + pref + g_bsum[blockIdx.x];
        g_off[j] = val;
        if (j < n) g_cur[j] = val;   // fold copy_cur here
    }
}

__global__ __launch_bounds__(256) void scatter_kernel(
    const int* __restrict__ edge_index, const int* __restrict__ edge_attr, int e)
{
    int i = blockIdx.x * 256 + threadIdx.x;
    if (i >= e) return;
    int src = __ldg(&edge_index[i]);
    int dst = __ldg(&edge_index[e + i]);
    int a0 = __ldg(&edge_attr[3 * i + 0]);
    int a1 = __ldg(&edge_attr[3 * i + 1]);
    int a2 = __ldg(&edge_attr[3 * i + 2]);
    int pos = atomicAdd(&g_cur[dst], 1);
    g_csr[pos] = make_int2(src, a0 * 25 + a1 * 5 + a2);
}

__global__ __launch_bounds__(256) void clear_pool_kernel(float* __restrict__ gout, int b)
{
    int i = blockIdx.x * 256 + threadIdx.x;
    if (i < b * 64) gout[i] = 0.f;
    if (i < b) g_cnt[i] = 0.f;
}

// ---------------------------------------------------------------------------
// Edge kernel (CSR): warp-per-node, unroll-2 (R11 body), 512-thread blocks
// for 100% occupancy (4 blocks/SM x 512 = 2048 threads; table 31.25KB x4 =
// 125KB smem). lane = float2 chunk.
// z = (1+eps)*h[nid] + sum relu(h[src] + table[combo]) -> g_agg.
// Block 0 zeroes g_stats.
// ---------------------------------------------------------------------------
__global__ __launch_bounds__(512) void edge_csr_kernel(
    const float* __restrict__ bond_emb_l, const float* __restrict__ epsp, int n)
{
    __shared__ __align__(16) float table[125 * 64];   // 31.25 KB

    if (blockIdx.x == 0 && threadIdx.x < 128) {
        g_stats[threadIdx.x] = 0.f;
        g_stats[128 + threadIdx.x] = 0.f;
        g_stats[256 + threadIdx.x] = 0.f;
    }

    const float4* b4 = (const float4*)bond_emb_l;     // [3,8,16] float4
    for (int t = threadIdx.x; t < 2000; t += 512) {
        int combo = t >> 4, c4 = t & 15;
        int a0 = combo / 25;
        int rr = combo - a0 * 25;
        int a1 = rr / 5;
        int a2 = rr - a1 * 5;
        float4 v0 = b4[a0 * 16 + c4];
        float4 v1 = b4[(8 + a1) * 16 + c4];
        float4 v2 = b4[(16 + a2) * 16 + c4];
        float4 s;
        s.x = v0.x + v1.x + v2.x;
        s.y = v0.y + v1.y + v2.y;
        s.z = v0.z + v1.z + v2.z;
        s.w = v0.w + v1.w + v2.w;
        ((float4*)table)[t] = s;
    }
    __syncthreads();

    float epsv = 1.0f + __ldg(epsp);
    int lane = threadIdx.x & 31;
    int w = threadIdx.x >> 5;     // 0..15
    const float2* th2 = (const float2*)table;
    const float2* h2 = (const float2*)g_h;

    for (int nid = blockIdx.x * 16 + w; nid < n; nid += gridDim.x * 16) {
        int s = __ldg(&g_off[nid]);
        int epos = __ldg(&g_off[nid + 1]);
        float2 a0 = make_float2(0.f, 0.f), a1 = make_float2(0.f, 0.f);
        int j = s;
        for (; j + 2 <= epos; j += 2) {
            int2 m0 = __ldg(&g_csr[j]);
            int2 m1 = __ldg(&g_csr[j + 1]);
            float2 e0 = th2[m0.y * 32 + lane];
            float2 e1 = th2[m1.y * 32 + lane];
            float2 h0 = h2[(size_t)m0.x * 32 + lane];
            float2 h1 = h2[(size_t)m1.x * 32 + lane];
            a0.x += fmaxf(h0.x + e0.x, 0.f);
            a0.y += fmaxf(h0.y + e0.y, 0.f);
            a1.x += fmaxf(h1.x + e1.x, 0.f);
            a1.y += fmaxf(h1.y + e1.y, 0.f);
        }
        if (j < epos) {
            int2 m0 = __ldg(&g_csr[j]);
            float2 e0 = th2[m0.y * 32 + lane];
            float2 h0 = h2[(size_t)m0.x * 32 + lane];
            a0.x += fmaxf(h0.x + e0.x, 0.f);
            a0.y += fmaxf(h0.y + e0.y, 0.f);
        }
        float2 hd = h2[(size_t)nid * 32 + lane];
        float2 z;
        z.x = fmaf(epsv, hd.x, a0.x + a1.x);
        z.y = fmaf(epsv, hd.y, a0.y + a1.y);
        ((float2*)g_agg)[(size_t)nid * 32 + lane] = z;
    }
}

// ---------------------------------------------------------------------------
// GEMM1 (tensor, B-stationary): z (g_agg) -> y1 = z@W1+b1 (g_y1). Fused BN1
// stats.
// ---------------------------------------------------------------------------
__global__ __launch_bounds__(256, 2) void gemm1_tc_kernel(
    const float* __restrict__ W1, const float* __restrict__ b1, int n, int ntiles)
{
    __shared__ float Zh[2][16][68];
    __shared__ float Zl[2][16][68];

    int tid = threadIdx.x;
    int wid = tid >> 5;
    int lane = tid & 31;
    int g = lane >> 2, tt = lane & 3;
    int nt0 = wid * 16;

    float wh[8][2][2], wl[8][2][2];
#pragma unroll
    for (int ks = 0; ks < 8; ks++)
#pragma unroll
        for (int t2 = 0; t2 < 2; t2++) {
            int col = nt0 + t2 * 8 + g;
            int k0 = ks * 8 + tt;
            float w0 = __ldg(&W1[k0 * 128 + col]);
            float w1 = __ldg(&W1[(k0 + 4) * 128 + col]);
            wh[ks][t2][0] = tf32_hi(w0); wl[ks][t2][0] = w0 - wh[ks][t2][0];
            wh[ks][t2][1] = tf32_hi(w1); wl[ks][t2][1] = w1 - wh[ks][t2][1];
        }
    float2 bias[2];
#pragma unroll
    for (int t2 = 0; t2 < 2; t2++)
        bias[t2] = *(const float2*)(b1 + nt0 + t2 * 8 + tt * 2);

    int srr = tid >> 4, sc4 = tid & 15;

    float sA[2][2] = {{0.f,0.f},{0.f,0.f}}, qA[2][2] = {{0.f,0.f},{0.f,0.f}};

    float4 pa = make_float4(0.f,0.f,0.f,0.f);
    int t = blockIdx.x;
    if (t < ntiles) {
        int row = t * 16 + srr;
        if (row < n) pa = ((const float4*)g_agg)[(size_t)row * 16 + sc4];
    }
    int buf = 0;
    for (; t < ntiles; t += gridDim.x) {
        {
            float* dh = &Zh[buf][srr][sc4 * 4];
            float* dl = &Zl[buf][srr][sc4 * 4];
            float h0 = tf32_hi(pa.x), h1 = tf32_hi(pa.y), h2 = tf32_hi(pa.z), h3 = tf32_hi(pa.w);
            dh[0] = h0; dh[1] = h1; dh[2] = h2; dh[3] = h3;
            dl[0] = pa.x - h0; dl[1] = pa.y - h1; dl[2] = pa.z - h2; dl[3] = pa.w - h3;
        }
        __syncthreads();

        int tn = t + gridDim.x;
        pa = make_float4(0.f,0.f,0.f,0.f);
        if (tn < ntiles) {
            int row = tn * 16 + srr;
            if (row < n) pa = ((const float4*)g_agg)[(size_t)row * 16 + sc4];
        }

        float acc[2][4] = {{0.f,0.f,0.f,0.f},{0.f,0.f,0.f,0.f}};
#pragma unroll
        for (int ks = 0; ks < 8; ks++) {
            int kc = ks * 8 + tt;
            float ah0 = Zh[buf][g][kc],     ah1 = Zh[buf][g + 8][kc];
            float ah2 = Zh[buf][g][kc + 4], ah3 = Zh[buf][g + 8][kc + 4];
            float al0 = Zl[buf][g][kc],     al1 = Zl[buf][g + 8][kc];
            float al2 = Zl[buf][g][kc + 4], al3 = Zl[buf][g + 8][kc + 4];
#pragma unroll
            for (int t2 = 0; t2 < 2; t2++) {
                mma8f(acc[t2], ah0, ah1, ah2, ah3, wh[ks][t2][0], wh[ks][t2][1]);
                mma8f(acc[t2], ah0, ah1, ah2, ah3, wl[ks][t2][0], wl[ks][t2][1]);
                mma8f(acc[t2], al0, al1, al2, al3, wh[ks][t2][0], wh[ks][t2][1]);
            }
        }

        int r0 = t * 16;
        int rA = r0 + g, rB = r0 + g + 8;
#pragma unroll
        for (int t2 = 0; t2 < 2; t2++) {
            int col = nt0 + t2 * 8 + tt * 2;
            float e0 = acc[t2][0] + bias[t2].x, o0 = acc[t2][1] + bias[t2].y;
            float e1 = acc[t2][2] + bias[t2].x, o1 = acc[t2][3] + bias[t2].y;
            if (rA < n) {
                *(float2*)(g_y1 + (size_t)rA * 128 + col) = make_float2(e0, o0);
                sA[t2][0] += e0; qA[t2][0] += e0 * e0;
                sA[t2][1] += o0; qA[t2][1] += o0 * o0;
            }
            if (rB < n) {
                *(float2*)(g_y1 + (size_t)rB * 128 + col) = make_float2(e1, o1);
                sA[t2][0] += e1; qA[t2][0] += e1 * e1;
                sA[t2][1] += o1; qA[t2][1] += o1 * o1;
            }
        }
        buf ^= 1;
    }

#pragma unroll
    for (int t2 = 0; t2 < 2; t2++)
#pragma unroll
        for (int j = 0; j < 2; j++) {
#pragma unroll
            for (int off = 4; off < 32; off <<= 1) {
                sA[t2][j] += __shfl_xor_sync(0xffffffffu, sA[t2][j], off);
                qA[t2][j] += __shfl_xor_sync(0xffffffffu, qA[t2][j], off);
            }
        }
    if (g == 0) {
#pragma unroll
        for (int t2 = 0; t2 < 2; t2++) {
            int col = nt0 + t2 * 8 + tt * 2;
            atomicAdd(&g_stats[col], sA[t2][0]);
            atomicAdd(&g_stats[col + 1], sA[t2][1]);
            atomicAdd(&g_stats[128 + col], qA[t2][0]);
            atomicAdd(&g_stats[128 + col + 1], qA[t2][1]);
        }
    }
}

// ---------------------------------------------------------------------------
// GEMM2 (tensor, B-stationary): t = relu(bn1(y1)) -> y2 = t@W2 + b2 -> g_agg.
// BN1 computed per block from g_stats. BN2 stats fused.
// ---------------------------------------------------------------------------
__global__ __launch_bounds__(256, 2) void gemm2_tc_kernel(
    const float* __restrict__ W2, const float* __restrict__ b2,
    const float* __restrict__ bn1_g, const float* __restrict__ bn1_b,
    float nInv, int n, int ntiles)
{
    __shared__ float Zh[2][16][132];
    __shared__ float Zl[2][16][132];
    __shared__ __align__(16) float bsc[128];
    __shared__ __align__(16) float bsh[128];

    int tid = threadIdx.x;
    int wid = tid >> 5;
    int lane = tid & 31;
    int g = lane >> 2, tt = lane & 3;
    int nt0 = wid * 8;

    if (tid < 128) {
        float mean = g_stats[tid] * nInv;
        float var = fmaxf(g_stats[128 + tid] * nInv - mean * mean, 0.f);
        float inv = rsqrtf(var + 1e-5f);
        float sc = __ldg(&bn1_g[tid]) * inv;
        bsc[tid] = sc;
        bsh[tid] = __ldg(&bn1_b[tid]) - mean * sc;
    }

    float wh[16][2], wl[16][2];
#pragma unroll
    for (int ks = 0; ks < 16; ks++) {
        int col = nt0 + g;
        int k0 = ks * 8 + tt;
        float w0 = __ldg(&W2[k0 * 64 + col]);
        float w1 = __ldg(&W2[(k0 + 4) * 64 + col]);
        wh[ks][0] = tf32_hi(w0); wl[ks][0] = w0 - wh[ks][0];
        wh[ks][1] = tf32_hi(w1); wl[ks][1] = w1 - wh[ks][1];
    }
    float2 bias = *(const float2*)(b2 + nt0 + tt * 2);

    int srr = tid >> 4, sc4b = (tid & 15) * 2;

    float sA[2] = {0.f, 0.f}, qA[2] = {0.f, 0.f};
    __syncthreads();

    float4 p0 = make_float4(0.f,0.f,0.f,0.f), p1 = p0;
    int t = blockIdx.x;
    if (t < ntiles) {
        int row = t * 16 + srr;
        if (row < n) {
            p0 = ((const float4*)g_y1)[(size_t)row * 32 + sc4b];
            p1 = ((const float4*)g_y1)[(size_t)row * 32 + sc4b + 1];
        }
    }
    int buf = 0;
    for (; t < ntiles; t += gridDim.x) {
        {
#pragma unroll
            for (int j = 0; j < 2; j++) {
                float4 y = j ? p1 : p0;
                int c4 = sc4b + j;
                float4 sc = ((const float4*)bsc)[c4];
                float4 sh = ((const float4*)bsh)[c4];
                float z0 = fmaxf(fmaf(y.x, sc.x, sh.x), 0.f);
                float z1 = fmaxf(fmaf(y.y, sc.y, sh.y), 0.f);
                float z2 = fmaxf(fmaf(y.z, sc.z, sh.z), 0.f);
                float z3 = fmaxf(fmaf(y.w, sc.w, sh.w), 0.f);
                float* dh = &Zh[buf][srr][c4 * 4];
                float* dl = &Zl[buf][srr][c4 * 4];
                float h0 = tf32_hi(z0), h1 = tf32_hi(z1), h2 = tf32_hi(z2), h3 = tf32_hi(z3);
                dh[0] = h0; dh[1] = h1; dh[2] = h2; dh[3] = h3;
                dl[0] = z0 - h0; dl[1] = z1 - h1; dl[2] = z2 - h2; dl[3] = z3 - h3;
            }
        }
        __syncthreads();

        int tn = t + gridDim.x;
        p0 = make_float4(0.f,0.f,0.f,0.f); p1 = p0;
        if (tn < ntiles) {
            int row = tn * 16 + srr;
            if (row < n) {
                p0 = ((const float4*)g_y1)[(size_t)row * 32 + sc4b];
                p1 = ((const float4*)g_y1)[(size_t)row * 32 + sc4b + 1];
            }
        }

        float acc[4] = {0.f, 0.f, 0.f, 0.f};
#pragma unroll
        for (int ks = 0; ks < 16; ks++) {
            int kc = ks * 8 + tt;
            float ah0 = Zh[buf][g][kc],     ah1 = Zh[buf][g + 8][kc];
            float ah2 = Zh[buf][g][kc + 4], ah3 = Zh[buf][g + 8][kc + 4];
            float al0 = Zl[buf][g][kc],     al1 = Zl[buf][g + 8][kc];
            float al2 = Zl[buf][g][kc + 4], al3 = Zl[buf][g + 8][kc + 4];
            mma8f(acc, ah0, ah1, ah2, ah3, wh[ks][0], wh[ks][1]);
            mma8f(acc, ah0, ah1, ah2, ah3, wl[ks][0], wl[ks][1]);
            mma8f(acc, al0, al1, al2, al3, wh[ks][0], wh[ks][1]);
        }

        int r0 = t * 16;
        int rA = r0 + g, rB = r0 + g + 8;
        int col = nt0 + tt * 2;
        float e0 = acc[0] + bias.x, o0 = acc[1] + bias.y;
        float e1 = acc[2] + bias.x, o1 = acc[3] + bias.y;
        if (rA < n) {
            *(float2*)(g_agg + (size_t)rA * 64 + col) = make_float2(e0, o0);
            sA[0] += e0; qA[0] += e0 * e0;
            sA[1] += o0; qA[1] += o0 * o0;
        }
        if (rB < n) {
            *(float2*)(g_agg + (size_t)rB * 64 + col) = make_float2(e1, o1);
            sA[0] += e1; qA[0] += e1 * e1;
            sA[1] += o1; qA[1] += o1 * o1;
        }
        buf ^= 1;
    }

#pragma unroll
    for (int j = 0; j < 2; j++) {
#pragma unroll
        for (int off = 4; off < 32; off <<= 1) {
            sA[j] += __shfl_xor_sync(0xffffffffu, sA[j], off);
            qA[j] += __shfl_xor_sync(0xffffffffu, qA[j], off);
        }
    }
    if (g == 0) {
        int col = nt0 + tt * 2;
        atomicAdd(&g_stats[256 + col], sA[0]);
        atomicAdd(&g_stats[256 + col + 1], sA[1]);
        atomicAdd(&g_stats[320 + col], qA[0]);
        atomicAdd(&g_stats[320 + col + 1], qA[1]);
    }
}

// ---------------------------------------------------------------------------
// BN2 apply. mode 0: relu -> g_h. mode 1: -> nodeout + fused pooling.
// ---------------------------------------------------------------------------
__global__ __launch_bounds__(256) void bn2_apply_kernel(
    const float* __restrict__ bn2_g, const float* __restrict__ bn2_b,
    float* __restrict__ nodeout, const int* __restrict__ batch,
    float* __restrict__ gout, float nInv, int n, int mode)
{
    __shared__ __align__(16) float bsc[64];
    __shared__ __align__(16) float bsh[64];
    if (threadIdx.x < 64) {
        int t = threadIdx.x;
        float mean = g_stats[256 + t] * nInv;
        float var = fmaxf(g_stats[320 + t] * nInv - mean * mean, 0.f);
        float inv = rsqrtf(var + 1e-5f);
        float sc = __ldg(&bn2_g[t]) * inv;
        bsc[t] = sc;
        bsh[t] = __ldg(&bn2_b[t]) - mean * sc;
    }
    __syncthreads();

    int i = blockIdx.x * 256 + threadIdx.x;
    if (i >= n * 16) return;
    int c = i & 15;
    float4 y = ((const float4*)g_agg)[i];
    float4 sc = ((const float4*)bsc)[c];
    float4 sh = ((const float4*)bsh)[c];
    float4 v;
    v.x = fmaf(y.x, sc.x, sh.x);
    v.y = fmaf(y.y, sc.y, sh.y);
    v.z = fmaf(y.z, sc.z, sh.z);
    v.w = fmaf(y.w, sc.w, sh.w);
    if (mode == 0) {
        v.x = fmaxf(v.x, 0.f); v.y = fmaxf(v.y, 0.f);
        v.z = fmaxf(v.z, 0.f); v.w = fmaxf(v.w, 0.f);
        ((float4*)g_h)[i] = v;
    } else {
        ((float4*)nodeout)[i] = v;
        int nid = i >> 4;
        int b = __ldg(&batch[nid]);
        red_add_v4(gout + (size_t)b * 64 + c * 4, v);
        if (c == 0) atomicAdd(&g_cnt[b], 1.0f);
    }
}

__global__ __launch_bounds__(256) void divide_kernel(float* __restrict__ gout, int b)
{
    int i = blockIdx.x * 256 + threadIdx.x;
    if (i < b * 64) gout[i] = gout[i] / (g_cnt[i >> 6] + 1e-9f);
}

// ---------------------------------------------------------------------------
// Launch
// ---------------------------------------------------------------------------
extern "C" void kernel_launch(void* const* d_in, const int* in_sizes, int n_in,
                              void* d_out, int out_size)
{
    const float* atom_emb = (const float*)d_in[0];
    const float* bond_emb = (const float*)d_in[1];
    const float* eps      = (const float*)d_in[2];
    const float* W1       = (const float*)d_in[3];
    const float* b1       = (const float*)d_in[4];
    const float* bn1_g    = (const float*)d_in[5];
    const float* bn1_b    = (const float*)d_in[6];
    const float* W2       = (const float*)d_in[7];
    const float* b2       = (const float*)d_in[8];
    const float* bn2_g    = (const float*)d_in[9];
    const float* bn2_b    = (const float*)d_in[10];
    const int* x_feat     = (const int*)d_in[11];
    const int* edge_index = (const int*)d_in[12];
    const int* edge_attr  = (const int*)d_in[13];
    const int* batch      = (const int*)d_in[14];

    int n = in_sizes[11] / 9;
    int e = in_sizes[12] / 2;
    int b = out_size / 64 - n;
    float* nodeout = (float*)d_out;
    float* gout = nodeout + (size_t)n * 64;

    int nodeGrid = (n * 16 + 255) / 256;
    int edgeBlocks = (e + 255) / 256;
    int scanBlocks = (n + 1023) / 1024;
    int ntiles = (n + 15) / 16;
    int gemmGrid = 296;
    int edgeGrid = 592;   // 4 blocks/SM x 148 SMs, 512 threads each (100% occ)
    float nInv = 1.0f / (float)n;

    atom_kernel<<<nodeGrid, 256>>>(atom_emb, x_feat, n);

    clear_off_kernel<<<(n + 256) / 256, 256>>>(n);
    hist_kernel<<<edgeBlocks, 256>>>(edge_index, e);
    scan_partial_kernel<<<scanBlocks, 1024>>>(n);
    scan_bsums_kernel<<<1, 32>>>(scanBlocks);
    scan_final_kernel<<<scanBlocks, 1024>>>(n);
    scatter_kernel<<<edgeBlocks, 256>>>(edge_index, edge_attr, e);

    clear_pool_kernel<<<(b * 64 + 255) / 256, 256>>>(gout, b);

    for (int l = 0; l < 4; l++) {
        edge_csr_kernel<<<edgeGrid, 512>>>(bond_emb + l * 1536, eps + l, n);
        gemm1_tc_kernel<<<gemmGrid, 256>>>(W1 + l * 64 * 128, b1 + l * 128, n, ntiles);
        gemm2_tc_kernel<<<gemmGrid, 256>>>(W2 + l * 128 * 64, b2 + l * 64,
                                           bn1_g + l * 128, bn1_b + l * 128, nInv, n, ntiles);
        bn2_apply_kernel<<<nodeGrid, 256>>>(bn2_g + l * 64, bn2_b + l * 64,
                                            nodeout, batch, gout, nInv, n, (l == 3) ? 1 : 0);
    }

    divide_kernel<<<(b * 64 + 255) / 256, 256>>>(gout, b);
}